// round 9
// baseline (speedup 1.0000x reference)
#include <cuda_runtime.h>
#include <cuda_fp16.h>

// VectorQuantizer: z [32,4096,64] fp32, W [512,64] fp32.
// Out fp32: z_q_st (8388608) | indices-as-float (131072) | loss (1).
//
// R9 == R8 retest (R8 hit a harness/driver init failure, not a kernel bug):
// 1024 threads/CTA (8 warps/SMSP) with warp-pair code-split; per-thread
// running-min threshold (provable candidate superset; no shfl chain in hot
// loop). Deferred exact rescore with the bitwise reference chain; fused
// fixed-point deterministic loss (proven in R7).

#define DIM       64
#define KCODES    512
#define NROWS     131072
#define ROWS_CTA  256
#define GRIDM     (NROWS / ROWS_CTA)     // 512
#define THREADS   1024
#define NELEM_ZQ  (NROWS * DIM)
#define SZ_STRIDE 66                     // fp32 row stride in smem (words)
#define SW_STRIDE 36                     // fp16-pair row stride (words)
#define CAP       12288                  // candidate entries

typedef unsigned int u32;
typedef unsigned long long u64;

__device__ u64 g_acc  = 0ull;            // fixed-point loss accumulator
__device__ u32 g_done = 0u;              // CTA completion counter

__device__ __forceinline__ u32 fflip(float x) {
    u32 u = __float_as_uint(x);
    return (u & 0x80000000u) ? ~u : (u | 0x80000000u);
}

// smem offsets (bytes)
#define OFF_SBEST 0
#define OFF_SRED  2048
#define OFF_SZ    10240
#define OFF_SW    (OFF_SZ + ROWS_CTA * SZ_STRIDE * 4)
#define OFF_WSQ   (OFF_SW + KCODES * SW_STRIDE * 4)
#define OFF_ZZ    (OFF_WSQ + KCODES * 4)
#define OFF_WID   (OFF_ZZ + ROWS_CTA * 4)
#define OFF_CAND  (OFF_WID + ROWS_CTA * 4)
#define OFF_CTL   (OFF_CAND + CAP * 4)
#define SMEM_TOT  (OFF_CTL + 16)

__global__ __launch_bounds__(THREADS, 1)
void vq_all(const float* __restrict__ z, const float* __restrict__ W,
            float* __restrict__ out, int out_size) {
    extern __shared__ char smraw[];
    u64*    sbest = (u64*)(smraw + OFF_SBEST);     // 256
    double* sred  = (double*)(smraw + OFF_SRED);   // 1024
    float*  sz    = (float*)(smraw + OFF_SZ);      // 256 x 66
    u32*    sW    = (u32*)(smraw + OFF_SW);        // 512 x 36 (fp16x2)
    float*  swsq  = (float*)(smraw + OFF_WSQ);     // 512
    float*  szz   = (float*)(smraw + OFF_ZZ);      // 256
    float*  swid  = (float*)(smraw + OFF_WID);     // 256
    u32*    scand = (u32*)(smraw + OFF_CAND);      // CAP
    u32*    sctl  = (u32*)(smraw + OFF_CTL);       // cnt, ovf

    const int tid  = threadIdx.x;
    const int lane = tid & 31;
    const int wid  = tid >> 5;                     // 0..31
    const int gid  = lane >> 2;
    const int tig  = lane & 3;
    const int rowbase = blockIdx.x * ROWS_CTA;
    const u32 FULL = 0xFFFFFFFFu;

    // ===== Phase 1: wsq via two coalesced 256-row chunks through sz =====
    #pragma unroll 1
    for (int c = 0; c < 2; c++) {
        const float2* Wg = (const float2*)(W + (size_t)c * 256 * DIM);
        for (int i = tid; i < 256 * (DIM / 2); i += THREADS) {
            int r = i >> 5, kw = i & 31;
            *(float2*)(sz + r * SZ_STRIDE + kw * 2) = Wg[i];
        }
        __syncthreads();
        if (tid < 256) {
            const float* w = sz + tid * SZ_STRIDE;
            float acc = 0.0f;
            #pragma unroll
            for (int k = 0; k < DIM; k++)
                acc = __fadd_rn(acc, __fmul_rn(w[k], w[k]));
            swsq[c * 256 + tid] = acc;   // exact sequential reference chain
        }
        __syncthreads();
    }

    // ===== Phase 2: wmax = max ||w_j|| (tree in sred scratch) =====
    float wmax;
    {
        float* fs = (float*)sred;
        fs[tid] = (tid < KCODES) ? sqrtf(swsq[tid]) : 0.0f;
        __syncthreads();
        #pragma unroll
        for (int s = 512; s > 0; s >>= 1) {
            if (tid < s) fs[tid] = fmaxf(fs[tid], fs[tid + s]);
            __syncthreads();
        }
        wmax = fs[0] * 1.0001f;
        __syncthreads();
    }

    // ===== Phase 3: stage z (overwrites sz), fp16 W, init =====
    {
        const float2* zg = (const float2*)(z + (size_t)rowbase * DIM);
        for (int i = tid; i < ROWS_CTA * (DIM / 2); i += THREADS) {
            int r = i >> 5, c2 = i & 31;
            *(float2*)(sz + r * SZ_STRIDE + c2 * 2) = zg[i];
        }
        for (int i = tid; i < KCODES * (DIM / 2); i += THREADS) {
            int j = i >> 5, kw = i & 31;
            float2 g = ((const float2*)W)[i];
            __half2 h = __float22half2_rn(g);
            sW[j * SW_STRIDE + kw] = *(u32*)&h;
        }
        if (tid < ROWS_CTA) sbest[tid] = ~0ull;
        if (tid == 0) { sctl[0] = 0; sctl[1] = 0; }
        __syncthreads();
    }

    // ===== Phase 4: exact zz per row + rigorous width =====
    if (tid < ROWS_CTA) {
        const float* zr = sz + tid * SZ_STRIDE;
        float acc = 0.0f;
        #pragma unroll
        for (int k = 0; k < DIM; k++)
            acc = __fadd_rn(acc, __fmul_rn(zr[k], zr[k]));
        szz[tid] = acc;
        float znorm = sqrtf(acc) * 1.0001f;
        swid[tid] = 4.1e-3f * znorm * wmax + 1.1e-6f * znorm + 4.0e-5f;
    }
    __syncthreads();

    // ===== Phase 5: A fragments; warp pair (w, w+16) shares a row tile =====
    const int rowwid = wid & 15;
    const int whalf  = wid >> 4;                   // 0: codes 0..255, 1: 256..511
    const int m0 = rowwid * 16 + gid;
    u32 A[4][4];
    #pragma unroll
    for (int kk = 0; kk < 4; kk++) {
        int kb = kk * 16;
        float2 p0 = *(float2*)(sz + m0 * SZ_STRIDE + kb + tig * 2);
        float2 p1 = *(float2*)(sz + (m0 + 8) * SZ_STRIDE + kb + tig * 2);
        float2 p2 = *(float2*)(sz + m0 * SZ_STRIDE + kb + 8 + tig * 2);
        float2 p3 = *(float2*)(sz + (m0 + 8) * SZ_STRIDE + kb + 8 + tig * 2);
        __half2 h;
        h = __float22half2_rn(p0); A[kk][0] = *(u32*)&h;
        h = __float22half2_rn(p1); A[kk][1] = *(u32*)&h;
        h = __float22half2_rn(p2); A[kk][2] = *(u32*)&h;
        h = __float22half2_rn(p3); A[kk][3] = *(u32*)&h;
    }

    // ===== Phase 6: filter, per-thread running-min threshold =====
    // superset proof: s_{j*} <= min_j s_j + width <= rmin_thread + width
    {
        const float widA = swid[m0], widB = swid[m0 + 8];
        float rminA = 3.0e38f, rminB = 3.0e38f;

        #pragma unroll 1
        for (int it = 0; it < 32; it++) {
            const int j0 = (whalf * 32 + it) * 8;
            float c0 = 0.f, c1 = 0.f, c2 = 0.f, c3 = 0.f;
            const u32* wrow = sW + (j0 + gid) * SW_STRIDE + tig;
            #pragma unroll
            for (int kk = 0; kk < 4; kk++) {
                u32 b0 = wrow[kk * 8];
                u32 b1 = wrow[kk * 8 + 4];
                asm volatile(
                    "mma.sync.aligned.m16n8k16.row.col.f32.f16.f16.f32 "
                    "{%0,%1,%2,%3}, {%4,%5,%6,%7}, {%8,%9}, {%0,%1,%2,%3};"
                    : "+f"(c0), "+f"(c1), "+f"(c2), "+f"(c3)
                    : "r"(A[kk][0]), "r"(A[kk][1]), "r"(A[kk][2]), "r"(A[kk][3]),
                      "r"(b0), "r"(b1));
            }
            const int jc = j0 + tig * 2;
            float w0 = swsq[jc], w1 = swsq[jc + 1];
            float s0 = __fsub_rn(w0, __fmul_rn(2.0f, c0));
            float s1 = __fsub_rn(w1, __fmul_rn(2.0f, c1));
            float s2 = __fsub_rn(w0, __fmul_rn(2.0f, c2));
            float s3 = __fsub_rn(w1, __fmul_rn(2.0f, c3));

            rminA = fminf(rminA, fminf(s0, s1));
            rminB = fminf(rminB, fminf(s2, s3));
            const float tA = rminA + widA, tB = rminB + widB;

            if (s0 <= tA) { u32 x = atomicAdd(&sctl[0], 1u);
                            if (x < CAP) scand[x] = ((u32)m0 << 9) | (u32)jc;
                            else atomicExch(&sctl[1], 1u); }
            if (s1 <= tA) { u32 x = atomicAdd(&sctl[0], 1u);
                            if (x < CAP) scand[x] = ((u32)m0 << 9) | (u32)(jc + 1);
                            else atomicExch(&sctl[1], 1u); }
            if (s2 <= tB) { u32 x = atomicAdd(&sctl[0], 1u);
                            if (x < CAP) scand[x] = ((u32)(m0 + 8) << 9) | (u32)jc;
                            else atomicExch(&sctl[1], 1u); }
            if (s3 <= tB) { u32 x = atomicAdd(&sctl[0], 1u);
                            if (x < CAP) scand[x] = ((u32)(m0 + 8) << 9) | (u32)(jc + 1);
                            else atomicExch(&sctl[1], 1u); }
        }
    }
    __syncthreads();

    // ===== Phase 7: deferred exact rescore (bitwise reference chain) =====
    if (sctl[1] == 0) {
        int n = min(sctl[0], (u32)CAP);
        for (int c = tid; c < n; c += THREADS) {
            u32 e = scand[c];
            int r = e >> 9, j = e & 511;
            const float* zr = sz + r * SZ_STRIDE;
            const float* wr = W + j * DIM;
            float acc = 0.0f;
            #pragma unroll
            for (int k = 0; k < DIM; k += 4) {
                float2 za = *(const float2*)(zr + k);
                float2 zb = *(const float2*)(zr + k + 2);
                float4 wv = *(const float4*)(wr + k);
                acc = __fmaf_rn(za.x, wv.x, acc);
                acc = __fmaf_rn(za.y, wv.y, acc);
                acc = __fmaf_rn(zb.x, wv.z, acc);
                acc = __fmaf_rn(zb.y, wv.w, acc);
            }
            float dist = __fsub_rn(__fadd_rn(szz[r], swsq[j]), __fmul_rn(2.0f, acc));
            atomicMin(&sbest[r], ((u64)fflip(dist) << 32) | (u32)j);
        }
    } else {
        // overflow fallback: warp-cooperative full exact scan (always correct)
        for (int r = wid; r < ROWS_CTA; r += THREADS / 32) {
            const float* zr = sz + r * SZ_STRIDE;
            u64 best = ~0ull;
            for (int j = lane; j < KCODES; j += 32) {
                const float* wr = W + j * DIM;
                float acc = 0.0f;
                #pragma unroll
                for (int k = 0; k < DIM; k += 4) {
                    float2 za = *(const float2*)(zr + k);
                    float2 zb = *(const float2*)(zr + k + 2);
                    float4 wv = *(const float4*)(wr + k);
                    acc = __fmaf_rn(za.x, wv.x, acc);
                    acc = __fmaf_rn(za.y, wv.y, acc);
                    acc = __fmaf_rn(zb.x, wv.z, acc);
                    acc = __fmaf_rn(zb.y, wv.w, acc);
                }
                float dist = __fsub_rn(__fadd_rn(szz[r], swsq[j]), __fmul_rn(2.0f, acc));
                best = min(best, ((u64)fflip(dist) << 32) | (u32)j);
            }
            #pragma unroll
            for (int off = 16; off > 0; off >>= 1)
                best = min(best, __shfl_xor_sync(FULL, best, off));
            if (lane == 0) atomicMin(&sbest[r], best);
        }
    }
    __syncthreads();

    // ===== Phase 8: epilogue (coalesced) + deterministic loss =====
    double dsum = 0.0;
    for (int i = tid; i < ROWS_CTA * DIM; i += THREADS) {
        int r = i >> 6, k = i & 63;
        int bj = (int)(sbest[r] & 0xFFFFFFFFull);
        float zv = sz[r * SZ_STRIDE + k];
        float wv = __ldg(W + bj * DIM + k);
        float st = __fadd_rn(zv, __fsub_rn(wv, zv));
        float df = __fsub_rn(zv, st);
        dsum += (double)__fmul_rn(df, df);
        out[(size_t)rowbase * DIM + i] = st;
    }
    if (tid < ROWS_CTA && out_size > NELEM_ZQ + rowbase + tid)
        out[NELEM_ZQ + rowbase + tid] = (float)(sbest[tid] & 0xFFFFFFFFull);

    sred[tid] = dsum;
    __syncthreads();
    #pragma unroll
    for (int s = THREADS / 2; s > 0; s >>= 1) {
        if (tid < s) sred[tid] += sred[tid + s];
        __syncthreads();
    }
    if (tid == 0) {
        // fixed-point (2^20) order-independent accumulation -> deterministic
        u64 part = (u64)__double2ll_rn(sred[0] * 1048576.0);
        atomicAdd(&g_acc, part);
        __threadfence();
        u32 t = atomicAdd(&g_done, 1u);
        if (t == GRIDM - 1) {                 // last CTA finalizes + resets
            u64 tot = atomicExch(&g_acc, 0ull);
            atomicExch(&g_done, 0u);
            double s = (double)tot * (1.0 / 1048576.0);
            int lp = NELEM_ZQ + NROWS;
            if (out_size > lp)
                out[lp] = (float)(0.25 * s / (double)NELEM_ZQ);
        }
    }
}

extern "C" void kernel_launch(void* const* d_in, const int* in_sizes, int n_in,
                              void* d_out, int out_size) {
    const float* z = (const float*)d_in[0];
    const float* W = (const float*)d_in[1];
    float* out = (float*)d_out;

    static bool attr_set = false;
    if (!attr_set) {
        cudaFuncSetAttribute(vq_all, cudaFuncAttributeMaxDynamicSharedMemorySize,
                             SMEM_TOT);
        attr_set = true;
    }

    vq_all<<<GRIDM, THREADS, SMEM_TOT>>>(z, W, out, out_size);
}